// round 15
// baseline (speedup 1.0000x reference)
#include <cuda_runtime.h>
#include <cuda_bf16.h>
#include <cuda_fp16.h>
#include <mma.h>
#include <math.h>

using namespace nvcuda;
typedef unsigned long long ull;

#define N_NODES 50000
#define NPAD    50048
#define E_EDGES 600000
#define B_GR    128
#define D       128
#define NHEAD   4
#define DH      32
#define NEG_SLOPE 0.2f
#define SCAN_NBLK ((N_NODES + 255) / 256)   // 196
#define EB ((E_EDGES + 255) / 256)          // 2344
#define WB ((N_NODES * 32 + 255) / 256)     // 6250

// ---------------- device scratch (zero-initialized at module load) ----------------
__device__ int    d_src[E_EDGES];
__device__ int    d_dst[E_EDGES];
__device__ int    d_gid[N_NODES];
__device__ int    d_count[N_NODES];          // self-cleaning: decode +1, fill -1
__device__ int    d_rowptr[N_NODES + 1];
__device__ int    d_col[E_EDGES];
__device__ float  d_z[N_NODES * D];
__device__ float  d_as[N_NODES * NHEAD];
__device__ float  d_ad[N_NODES * NHEAD];
__device__ float  d_hA[N_NODES * D];
__device__ float  d_hB[N_NODES * D];
__device__ __half d_hhA[NPAD * D];           // fp16 hi mirror of hA (pad rows stay 0)
__device__ __half d_hlA[NPAD * D];           // fp16 lo residual of hA
__device__ __half d_hhB[NPAD * D];
__device__ __half d_hlB[NPAD * D];
__device__ __half d_Whi[2 * D * D];          // W layers 1,2 fp16 hi
__device__ __half d_Wlo[2 * D * D];          // W layers 1,2 fp16 lo residual
__device__ float  d_z0[D];
__device__ float  d_gsum[B_GR * D];
__device__ int    d_gcnt[B_GR];

// ---------------- helpers ----------------
__device__ __forceinline__ float lrelu(float x) { return x >= 0.f ? x : NEG_SLOPE * x; }
__device__ __forceinline__ float eluf(float x)  { return x > 0.f ? x : expm1f(x); }

// write fp16 hi/lo split of a float4 at half-index base (8B-aligned)
__device__ __forceinline__ void store_hilo(__half* hh, __half* hl, int idx4, float4 o) {
    __half h0 = __float2half_rn(o.x), h1 = __float2half_rn(o.y);
    __half h2 = __float2half_rn(o.z), h3 = __float2half_rn(o.w);
    __half l0 = __float2half_rn(o.x - __half2float(h0));
    __half l1 = __float2half_rn(o.y - __half2float(h1));
    __half l2 = __float2half_rn(o.z - __half2float(h2));
    __half l3 = __float2half_rn(o.w - __half2float(h3));
    ((__half2*)hh)[idx4 * 2]     = __halves2half2(h0, h1);
    ((__half2*)hh)[idx4 * 2 + 1] = __halves2half2(h2, h3);
    ((__half2*)hl)[idx4 * 2]     = __halves2half2(l0, l1);
    ((__half2*)hl)[idx4 * 2 + 1] = __halves2half2(l2, l3);
}

// int64 LE with values < 2^31 -> every odd 32-bit word is 0.
__device__ __forceinline__ int detect_is64(const int* __restrict__ edge32) {
    int is64 = 1;
#pragma unroll
    for (int q = 0; q < 8; q++) is64 &= (edge32[2 * q + 1] == 0);
    return is64;
}

// ---------------- decode + histogram + z0 + gsum zero + W fp16 split ----------------
__global__ void decode_k(const void* __restrict__ edge, const void* __restrict__ ptr,
                         const float* __restrict__ emb, const float* __restrict__ W0) {
    int b = blockIdx.x;
    int t = threadIdx.x;
    __shared__ int s_is64;
    if (t == 0) s_is64 = detect_is64((const int*)edge);
    __syncthreads();
    int is64 = s_is64;

    if (b < EB) {
        int e = b * 256 + t;
        if (e >= E_EDGES) return;
        int s, d;
        if (is64) {
            const long long* p = (const long long*)edge;
            s = (int)p[e]; d = (int)p[E_EDGES + e];
        } else {
            const int* p = (const int*)edge;
            s = p[e]; d = p[E_EDGES + e];
        }
        d_src[e] = s; d_dst[e] = d;
        atomicAdd(&d_count[d], 1);
    } else if (b < EB + SCAN_NBLK) {
        int n = (b - EB) * 256 + t;
        if (n >= N_NODES) return;
        d_gid[n] = is64 ? (int)((const long long*)ptr)[n] : ((const int*)ptr)[n];
    } else if (b < EB + SCAN_NBLK + 64) {
        int i = (b - EB - SCAN_NBLK) * 256 + t;
        if (i < B_GR * D) d_gsum[i] = 0.f;
        if (i < B_GR)     d_gcnt[i] = 0;
    } else if (b == EB + SCAN_NBLK + 64) {
        if (t < D) {
            float acc = 0.f;
            for (int k = 0; k < D; k++) acc += emb[k] * W0[k * D + t];
            d_z0[t] = acc;
        }
    } else {
        // W fp16 hi/lo split: layers 1,2 = lin_w[16384 .. 49151], 32768 elems
        int bb = b - (EB + SCAN_NBLK + 65);     // 0..7
        int base = bb * 4096 + t * 16;
#pragma unroll
        for (int q = 0; q < 16; q++) {
            int ii = base + q;
            float f = W0[D * D + ii];
            __half h = __float2half_rn(f);
            d_Whi[ii] = h;
            d_Wlo[ii] = __float2half_rn(f - __half2float(h));
        }
    }
}

// ---------------- single-kernel exclusive scan (redundant block prefixes) ----------------
__global__ void scan_k() {
    __shared__ int red[256];
    __shared__ int sh[256];
    int b = blockIdx.x;
    int t = threadIdx.x;
    if (b == 0 && t == 0) d_rowptr[N_NODES] = E_EDGES;

    int limit = b * 256;
    int psum = 0;
    for (int i = t; i < limit; i += 256) psum += d_count[i];
    red[t] = psum;
    __syncthreads();
    for (int off = 128; off > 0; off >>= 1) {
        if (t < off) red[t] += red[t + off];
        __syncthreads();
    }
    int pre = red[0];

    int i = limit + t;
    int v = (i < N_NODES) ? d_count[i] : 0;
    sh[t] = v;
    __syncthreads();
    for (int off = 1; off < 256; off <<= 1) {
        int tv = (t >= off) ? sh[t - off] : 0;
        __syncthreads();
        sh[t] += tv;
        __syncthreads();
    }
    if (i < N_NODES) d_rowptr[i] = pre + sh[t] - v;  // exclusive
}

// ---------------- CSR fill (self-cleaning counters) + layer-1 shortcut + mirrors ----------------
__global__ void fill_h1_k(const float* __restrict__ emb) {
    int b = blockIdx.x;
    if (b < EB) {
        int e = b * 256 + threadIdx.x;
        if (e >= E_EDGES) return;
        int d = d_dst[e];
        int old = atomicSub(&d_count[d], 1);     // counters return to 0 for next run
        d_col[d_rowptr[d] + old - 1] = d_src[e];
    } else {
        int i = (b - EB) * 256 + threadIdx.x;    // float4 index
        if (i >= N_NODES * 32) return;
        int n = i >> 5, q = i & 31;
        int deg = d_rowptr[n + 1] - d_rowptr[n];
        float m = (float)(deg + 2);              // 1 + deg_total
        float4 z = ((const float4*)d_z0)[q];
        float4 e4 = ((const float4*)emb)[q];
        float4 o;
        o.x = eluf(m * z.x) + e4.x;
        o.y = eluf(m * z.y) + e4.y;
        o.z = eluf(m * z.z) + e4.z;
        o.w = eluf(m * z.w) + e4.w;
        ((float4*)d_hA)[i] = o;
        store_hilo(d_hhA, d_hlA, i, o);
    }
}

// ---------------- GEMM: z = h @ W via wmma fp16 with 3-term hi/lo split ----------------
// Block 128x128, 512 threads = 16 warps (wm 0..3, wn 0..3), warp tile 32x32.
// Fragments loaded directly from global (L1/L2-cached). acc fp32.
__global__ __launch_bounds__(512) void gemm_k(int l, int sel) {
    const __half* __restrict__ Hh = sel ? d_hhB : d_hhA;
    const __half* __restrict__ Hl = sel ? d_hlB : d_hlA;
    const __half* __restrict__ Wh = d_Whi + l * D * D;
    const __half* __restrict__ Wl = d_Wlo + l * D * D;
    int wid = threadIdx.x >> 5;
    int lane = threadIdx.x & 31;
    int wm = wid >> 2, wn = wid & 3;
    int row0 = blockIdx.x * 128;
    int rbase = row0 + wm * 32;
    int cbase = wn * 32;

    wmma::fragment<wmma::accumulator, 16, 16, 16, float> acc[2][2];
#pragma unroll
    for (int i = 0; i < 2; i++)
#pragma unroll
        for (int j = 0; j < 2; j++) wmma::fill_fragment(acc[i][j], 0.f);

#pragma unroll
    for (int k = 0; k < D; k += 16) {
        wmma::fragment<wmma::matrix_a, 16, 16, 16, __half, wmma::row_major> ah[2], al[2];
#pragma unroll
        for (int i = 0; i < 2; i++) {
            wmma::load_matrix_sync(ah[i], Hh + (rbase + i * 16) * D + k, D);
            wmma::load_matrix_sync(al[i], Hl + (rbase + i * 16) * D + k, D);
        }
#pragma unroll
        for (int j = 0; j < 2; j++) {
            wmma::fragment<wmma::matrix_b, 16, 16, 16, __half, wmma::row_major> bh, bl;
            wmma::load_matrix_sync(bh, Wh + k * D + cbase + j * 16, D);
            wmma::load_matrix_sync(bl, Wl + k * D + cbase + j * 16, D);
#pragma unroll
            for (int i = 0; i < 2; i++) {
                wmma::mma_sync(acc[i][j], ah[i], bh, acc[i][j]);
                wmma::mma_sync(acc[i][j], ah[i], bl, acc[i][j]);
                wmma::mma_sync(acc[i][j], al[i], bh, acc[i][j]);
            }
        }
    }

    if (row0 + 128 <= N_NODES) {
#pragma unroll
        for (int i = 0; i < 2; i++)
#pragma unroll
            for (int j = 0; j < 2; j++)
                wmma::store_matrix_sync(d_z + (rbase + i * 16) * D + cbase + j * 16,
                                        acc[i][j], D, wmma::mem_row_major);
    } else {
        __shared__ float buf[16][256];
#pragma unroll
        for (int i = 0; i < 2; i++)
#pragma unroll
            for (int j = 0; j < 2; j++) {
                wmma::store_matrix_sync(buf[wid], acc[i][j], 16, wmma::mem_row_major);
                __syncwarp();
#pragma unroll
                for (int t8 = 0; t8 < 8; t8++) {
                    int e = t8 * 32 + lane;
                    int r = e >> 4, c = e & 15;
                    int grow = rbase + i * 16 + r;
                    if (grow < N_NODES) d_z[grow * D + cbase + j * 16 + c] = buf[wid][e];
                }
                __syncwarp();
            }
    }
}

// ---------------- attention logits a_s, a_d ----------------
__global__ void att_k(const float* __restrict__ att_s, const float* __restrict__ att_d) {
    int warp = (blockIdx.x * blockDim.x + threadIdx.x) >> 5;
    if (warp >= N_NODES) return;
    int lane = threadIdx.x & 31;
    int head = lane >> 3;
    float4 z = ((const float4*)d_z)[warp * 32 + lane];
    float4 s = ((const float4*)att_s)[head * 8 + (lane & 7)];
    float4 t = ((const float4*)att_d)[head * 8 + (lane & 7)];
    float ps = z.x * s.x + z.y * s.y + z.z * s.z + z.w * s.w;
    float pd = z.x * t.x + z.y * t.y + z.z * t.z + z.w * t.w;
#pragma unroll
    for (int o = 4; o >= 1; o >>= 1) {
        ps += __shfl_xor_sync(0xffffffffu, ps, o);
        pd += __shfl_xor_sync(0xffffffffu, pd, o);
    }
    if ((lane & 7) == 0) {
        d_as[warp * 4 + head] = ps;
        d_ad[warp * 4 + head] = pd;
    }
}

// ---------------- fused ONLINE softmax + aggregation + elu + residual + mirrors ----------------
__global__ void agg_k(int sel) {
    const float* __restrict__ hin = sel ? d_hB : d_hA;
    float* __restrict__ hout = sel ? d_hA : d_hB;
    __half* __restrict__ hhout = sel ? d_hhA : d_hhB;
    __half* __restrict__ hlout = sel ? d_hlA : d_hlB;
    int n = (blockIdx.x * blockDim.x + threadIdx.x) >> 5;
    if (n >= N_NODES) return;
    int lane = threadIdx.x & 31;
    int head = lane >> 3;

    float ad = d_ad[n * 4 + head];
    float amax = lrelu(d_as[n * 4 + head] + ad);   // self logit
    int beg = d_rowptr[n], end = d_rowptr[n + 1];

    float den = 1.f;                               // exp(self - self)
    float4 zv = ((const float4*)d_z)[n * 32 + lane];
    float4 S0 = zv;
    float4 S1 = zv;

#pragma unroll 2
    for (int e = beg; e < end; e++) {
        int s = __ldg(&d_col[e]);
        float l = lrelu(__ldg(&d_as[s * 4 + head]) + ad);
        float nm = fmaxf(amax, l);
        float c = __expf(amax - nm);
        float w = __expf(l - nm);
        amax = nm;
        float4 z2 = ((const float4*)d_z)[s * 32 + lane];
        den = fmaf(den, c, w);
        S0.x += z2.x; S0.y += z2.y; S0.z += z2.z; S0.w += z2.w;
        S1.x = fmaf(S1.x, c, w * z2.x);
        S1.y = fmaf(S1.y, c, w * z2.y);
        S1.z = fmaf(S1.z, c, w * z2.z);
        S1.w = fmaf(S1.w, c, w * z2.w);
    }
    float inv = 1.f / den;
    float4 r = ((const float4*)hin)[n * 32 + lane];
    float4 o;
    o.x = eluf(fmaf(S1.x, inv, S0.x)) + r.x;
    o.y = eluf(fmaf(S1.y, inv, S0.y)) + r.y;
    o.z = eluf(fmaf(S1.z, inv, S0.z)) + r.z;
    o.w = eluf(fmaf(S1.w, inv, S0.w)) + r.w;
    int i = n * 32 + lane;
    ((float4*)hout)[i] = o;
    store_hilo(hhout, hlout, i, o);
}

// ---------------- graph readout ----------------
__global__ void readout_k() {
    int warp = (blockIdx.x * blockDim.x + threadIdx.x) >> 5;
    int lane = threadIdx.x & 31;
    int n0 = warp * 64;
    if (n0 >= N_NODES) return;
    int n1 = min(n0 + 64, N_NODES);
    int gcur = d_gid[n0];
    float4 acc = make_float4(0.f, 0.f, 0.f, 0.f);
    int run = 0;
    for (int n = n0; n < n1; n++) {
        int g = d_gid[n];
        if (g != gcur) {
            atomicAdd(&d_gsum[gcur * D + lane * 4 + 0], acc.x);
            atomicAdd(&d_gsum[gcur * D + lane * 4 + 1], acc.y);
            atomicAdd(&d_gsum[gcur * D + lane * 4 + 2], acc.z);
            atomicAdd(&d_gsum[gcur * D + lane * 4 + 3], acc.w);
            if (lane == 0) atomicAdd(&d_gcnt[gcur], run);
            acc = make_float4(0.f, 0.f, 0.f, 0.f);
            run = 0; gcur = g;
        }
        float4 v = ((const float4*)d_hA)[n * 32 + lane];
        acc.x += v.x; acc.y += v.y; acc.z += v.z; acc.w += v.w;
        run++;
    }
    atomicAdd(&d_gsum[gcur * D + lane * 4 + 0], acc.x);
    atomicAdd(&d_gsum[gcur * D + lane * 4 + 1], acc.y);
    atomicAdd(&d_gsum[gcur * D + lane * 4 + 2], acc.z);
    atomicAdd(&d_gsum[gcur * D + lane * 4 + 3], acc.w);
    if (lane == 0) atomicAdd(&d_gcnt[gcur], run);
}

// ---------------- MLP readout ----------------
__global__ void mlp_k(const float* __restrict__ w0, const float* __restrict__ b0,
                      const float* __restrict__ w1, const float* __restrict__ b1,
                      float* __restrict__ y) {
    int b = blockIdx.x;
    int j = threadIdx.x;            // 64 hidden units
    float inv = 1.f / fmaxf((float)d_gcnt[b], 1.f);
    float acc = b0[j];
    for (int k = 0; k < D; k++) {
        float g = fmaxf(d_gsum[b * D + k] * inv, 0.f);
        acc = fmaf(g, w0[k * 64 + j], acc);
    }
    float t = fmaxf(acc, 0.f) * w1[j];
    __shared__ float sh[64];
    sh[j] = t;
    __syncthreads();
    for (int off = 32; off > 0; off >>= 1) {
        if (j < off) sh[j] += sh[j + off];
        __syncthreads();
    }
    if (j == 0) y[b] = sh[0] + b1[0];
}

// ---------------- launcher ----------------
extern "C" void kernel_launch(void* const* d_in, const int* in_sizes, int n_in,
                              void* d_out, int out_size) {
    const void*  edge  = d_in[1];
    const void*  ptr   = d_in[2];
    const float* emb   = (const float*)d_in[3];
    const float* lin_w = (const float*)d_in[4];
    const float* att_s = (const float*)d_in[5];
    const float* att_d = (const float*)d_in[6];
    const float* w0    = (const float*)d_in[7];
    const float* b0    = (const float*)d_in[8];
    const float* w1    = (const float*)d_in[9];
    const float* b1    = (const float*)d_in[10];
    float* y = (float*)d_out;

    decode_k<<<EB + SCAN_NBLK + 65 + 8, 256>>>(edge, ptr, emb, lin_w);
    scan_k<<<SCAN_NBLK, 256>>>();
    fill_h1_k<<<EB + WB, 256>>>(emb);

    for (int l = 1; l < 3; l++) {
        int sel = l - 1;   // 0: hA->hB, 1: hB->hA
        gemm_k<<<(N_NODES + 127) / 128, 512>>>(l - 1, sel);
        att_k<<<WB, 256>>>(att_s + l * NHEAD * DH, att_d + l * NHEAD * DH);
        agg_k<<<WB, 256>>>(sel);
    }

    readout_k<<<((N_NODES + 63) / 64 * 32 + 255) / 256, 256>>>();
    mlp_k<<<B_GR, 64>>>(w0, b0, w1, b1, y);
}